// round 8
// baseline (speedup 1.0000x reference)
#include <cuda_runtime.h>
#include <math.h>

// Problem constants
#define B_  256
#define S_  256
#define H_  512
#define H2_ 1024
#define O_  512

// ---------------------------------------------------------------------------
// Scratch (device globals)
// ---------------------------------------------------------------------------
__device__ float g_xe  [(size_t)S_ * B_ * H_ ];
__device__ float g_Gx  [(size_t)S_ * B_ * H2_];
__device__ float g_Cx  [(size_t)S_ * B_ * H_ ];
__device__ float g_hall[(size_t)S_ * B_ * H_ ];
__device__ float g_h   [B_ * H_];
__device__ float g_z   [B_ * H_];
__device__ float g_rh  [B_ * H_];

// Per-group barrier counters (8 groups, padded 128B apart)
__device__ unsigned g_gcnt[8 * 32];

// ---------------------------------------------------------------------------
// f32x2 packed math helpers
// ---------------------------------------------------------------------------
typedef unsigned long long ull;

#define FMA2(d, a, b) \
    asm("fma.rn.f32x2 %0, %1, %2, %3;" : "=l"(d) : "l"(a), "l"(b), "l"(d))

__device__ __forceinline__ ull splat2(float x) {
    ull d;
    asm("mov.b64 %0, {%1, %1};" : "=l"(d) : "r"(__float_as_uint(x)));
    return d;
}
__device__ __forceinline__ float2 unpack2(ull v) {
    float2 r;
    asm("mov.b64 {%0, %1}, %2;" : "=f"(r.x), "=f"(r.y) : "l"(v));
    return r;
}

__device__ __forceinline__ float sigm(float x) {
    return __fdividef(1.0f, 1.0f + __expf(-x));
}
__device__ __forceinline__ float tanh_fast(float x) {
    return 1.0f - 2.0f * __fdividef(1.0f, __expf(2.0f * x) + 1.0f);
}

// ---------------------------------------------------------------------------
// Group barrier (16 blocks/group): REDG arrival, monotonic-count wait.
// ---------------------------------------------------------------------------
__device__ __forceinline__ void group_sync(int grp, unsigned target) {
    __threadfence();
    __syncthreads();
    if (threadIdx.x == 0) {
        unsigned* cp = &g_gcnt[grp * 32];
        asm volatile("red.global.gpu.add.u32 [%0], %1;"
                     :: "l"(cp), "r"(1u) : "memory");
        unsigned v;
        do {
            asm volatile("ld.acquire.gpu.u32 %0, [%1];" : "=r"(v) : "l"(cp));
        } while (v < target);
    }
    __syncthreads();
}

// ---------------------------------------------------------------------------
// Big SGEMM (proven): C[M,N] = A[M,512] @ Bw[N,512]^T + bias
// ---------------------------------------------------------------------------
#define TBM 128
#define TBN 128
#define TBK 16
#define LDT 132

__global__ __launch_bounds__(256, 2)
void sgemm_big(int Asel, const float* __restrict__ Bw, int ldb,
               const float* __restrict__ bias, int mode,
               float* __restrict__ yout) {
    __shared__ float As[TBK * LDT];
    __shared__ float Bs[TBK * LDT];

    const int tid = threadIdx.x;
    const int ty  = tid >> 4;
    const int tx  = tid & 15;
    const int m0  = blockIdx.y * TBM;
    const int n0  = blockIdx.x * TBN;

    const float* A = Asel ? g_hall : g_xe;

    ull acc[4][8];
    #pragma unroll
    for (int i = 0; i < 4; i++)
        #pragma unroll
        for (int j = 0; j < 8; j++) acc[i][j] = 0ull;

    for (int k0 = 0; k0 < H_; k0 += TBK) {
        #pragma unroll
        for (int it = 0; it < 2; it++) {
            int idx = tid + it * 256;
            int r   = idx >> 2;
            int kq  = idx & 3;
            float4 av = *(const float4*)(A  + (size_t)(m0 + r) * H_ + k0 + kq * 4);
            float4 bv = *(const float4*)(Bw + (size_t)(n0 + r) * ldb + k0 + kq * 4);
            As[(kq * 4 + 0) * LDT + r] = av.x;
            As[(kq * 4 + 1) * LDT + r] = av.y;
            As[(kq * 4 + 2) * LDT + r] = av.z;
            As[(kq * 4 + 3) * LDT + r] = av.w;
            Bs[(kq * 4 + 0) * LDT + r] = bv.x;
            Bs[(kq * 4 + 1) * LDT + r] = bv.y;
            Bs[(kq * 4 + 2) * LDT + r] = bv.z;
            Bs[(kq * 4 + 3) * LDT + r] = bv.w;
        }
        __syncthreads();

        #pragma unroll
        for (int kk = 0; kk < TBK; kk++) {
            ulonglong2 a01 = *(const ulonglong2*)&As[kk * LDT + ty * 8];
            ulonglong2 a23 = *(const ulonglong2*)&As[kk * LDT + ty * 8 + 4];
            float4 bl  = *(const float4*)&Bs[kk * LDT + tx * 8];
            float4 bh4 = *(const float4*)&Bs[kk * LDT + tx * 8 + 4];
            ull ap[4] = {a01.x, a01.y, a23.x, a23.y};
            float bsc[8] = {bl.x, bl.y, bl.z, bl.w, bh4.x, bh4.y, bh4.z, bh4.w};
            #pragma unroll
            for (int j = 0; j < 8; j++) {
                ull bb = splat2(bsc[j]);
                #pragma unroll
                for (int i = 0; i < 4; i++) FMA2(acc[i][j], ap[i], bb);
            }
        }
        __syncthreads();
    }

    #pragma unroll
    for (int i = 0; i < 4; i++) {
        #pragma unroll
        for (int j = 0; j < 8; j++) {
            float2 v = unpack2(acc[i][j]);
            int n  = n0 + tx * 8 + j;
            float bval = bias[n];
            int mA = m0 + ty * 8 + i * 2;
            int mB = mA + 1;
            float oA = v.x + bval, oB = v.y + bval;
            if (mode == 0) {
                g_Gx[(size_t)mA * H2_ + n] = oA;
                g_Gx[(size_t)mB * H2_ + n] = oB;
            } else if (mode == 1) {
                g_Cx[(size_t)mA * H_ + n] = oA;
                g_Cx[(size_t)mB * H_ + n] = oB;
            } else {
                int sA = mA >> 8, bA = mA & 255;
                int sB = mB >> 8, bB = mB & 255;
                yout[((size_t)bA * S_ + sA) * O_ + n] = oA;
                yout[((size_t)bB * S_ + sB) * O_ + n] = oB;
            }
        }
    }
}

// ---------------------------------------------------------------------------
// Persistent recurrent kernel, 128 blocks x 256 threads, group barriers.
// Block (mt=bid>>4, nt=bid&15):
//   gate tile:  m [mt*32,+32), n [nt*64,+64) of 1024; thread tile 2m x 4n
//   cand tile:  m [mt*32,+32), n [nt*32,+32) of 512;  thread tile 2m x 2n
// Activation panel stored DUPLICATED: [k][2*m] with (a,a) pairs, so one
// LDS.128 yields both FMA2 a-operands with no splat MOVs.
//   gate inner: 1 LDS.128 + 1 LDS.128 + 4 FMA2 = 6 issues/k  (was 8)
//   cand inner: 1 LDS.128 + 1 LDS.64  + 2 FMA2 = 4 issues/k  (was 6)
// ---------------------------------------------------------------------------
#define WGS_LD 64
#define WHS_LD 32
#define APL2   68                           // duplicated panel row (floats)
#define WGS_OFF 0
#define WHS_OFF (512 * WGS_LD)              // 32768 floats
#define AP_OFF  (WHS_OFF + 512 * WHS_LD)    // 49152 floats
#define AP_BUF  (64 * APL2)                 // 4352 floats
#define PERSIST_SMEM ((AP_OFF + 2 * AP_BUF) * 4)   // 231424 bytes

__global__ __launch_bounds__(256, 1)
void gru_persist(const float* __restrict__ Wg, const float* __restrict__ Wh) {
    extern __shared__ float sm[];
    float* Wgs = sm + WGS_OFF;
    float* Whs = sm + WHS_OFF;
    float* AP  = sm + AP_OFF;

    const int tid = threadIdx.x;
    const int bid = blockIdx.x;
    const int mt  = bid >> 4;
    const int nt  = bid & 15;
    const int ty  = tid >> 4;      // m-pair index: rows ty*2, ty*2+1
    const int tx  = tid & 15;

    // init: zero h, load weight slices
    {
        int base = (bid * 256 + tid) * 4;
        *(float4*)&g_h[base] = make_float4(0.f, 0.f, 0.f, 0.f);
    }
    for (int idx = tid; idx < 64 * 128; idx += 256) {
        int j  = idx >> 7;
        int k4 = idx & 127;
        float4 v = *(const float4*)(Wg + (size_t)(nt * 64 + j) * H2_ + H_ + k4 * 4);
        Wgs[(k4 * 4 + 0) * WGS_LD + j] = v.x;
        Wgs[(k4 * 4 + 1) * WGS_LD + j] = v.y;
        Wgs[(k4 * 4 + 2) * WGS_LD + j] = v.z;
        Wgs[(k4 * 4 + 3) * WGS_LD + j] = v.w;
    }
    for (int idx = tid; idx < 32 * 128; idx += 256) {
        int j  = idx >> 7;
        int k4 = idx & 127;
        float4 v = *(const float4*)(Wh + (size_t)(nt * 32 + j) * H2_ + H_ + k4 * 4);
        Whs[(k4 * 4 + 0) * WHS_LD + j] = v.x;
        Whs[(k4 * 4 + 1) * WHS_LD + j] = v.y;
        Whs[(k4 * 4 + 2) * WHS_LD + j] = v.z;
        Whs[(k4 * 4 + 3) * WHS_LD + j] = v.w;
    }
    unsigned tgt = 0;
    group_sync(mt, tgt += 16);

    const float* hrow  = g_h  + (size_t)mt * 32 * H_;
    const float* rhrow = g_rh + (size_t)mt * 32 * H_;

    // per-thread panel-load coords (two float4 loads per chunk)
    const int pm0 = tid >> 4;            // 0..15
    const int pk0 = (tid & 15) * 4;      // 0..60
    const int pm1 = pm0 + 16;            // 16..31
    const int m0g = mt * 32 + ty * 2;    // global m for this thread's outputs
    const int nbg = nt * 64 + tx * 4;    // gate n base
    const int nbc = nt * 32 + tx * 2;    // cand n base

    for (int t = 0; t < S_; t++) {
        // ===================== GATE PHASE =====================
        float4 pf0 = __ldcg((const float4*)(hrow + (size_t)pm0 * H_ + pk0));
        float4 pf1 = __ldcg((const float4*)(hrow + (size_t)pm1 * H_ + pk0));
        const float* Gxt = g_Gx + (size_t)t * B_ * H2_;
        float4 gx0 = __ldcg((const float4*)(Gxt + (size_t)m0g * H2_ + nbg));
        float4 gx1 = __ldcg((const float4*)(Gxt + (size_t)(m0g + 1) * H2_ + nbg));
        float4 hv0 = make_float4(0.f,0.f,0.f,0.f), hv1 = hv0;
        if (nt >= 8) {
            int n2 = nbg - H_;
            hv0 = __ldcg((const float4*)(g_h + m0g * H_ + n2));
            hv1 = __ldcg((const float4*)(g_h + (m0g + 1) * H_ + n2));
        }

        ull a00 = 0ull, a01 = 0ull, a10 = 0ull, a11 = 0ull;
        #pragma unroll 1
        for (int c = 0; c < 8; c++) {
            float* buf = AP + (c & 1) * AP_BUF;
            {
                int kq = pk0;
                *(float2*)(buf + (kq + 0) * APL2 + pm0 * 2) = make_float2(pf0.x, pf0.x);
                *(float2*)(buf + (kq + 1) * APL2 + pm0 * 2) = make_float2(pf0.y, pf0.y);
                *(float2*)(buf + (kq + 2) * APL2 + pm0 * 2) = make_float2(pf0.z, pf0.z);
                *(float2*)(buf + (kq + 3) * APL2 + pm0 * 2) = make_float2(pf0.w, pf0.w);
                *(float2*)(buf + (kq + 0) * APL2 + pm1 * 2) = make_float2(pf1.x, pf1.x);
                *(float2*)(buf + (kq + 1) * APL2 + pm1 * 2) = make_float2(pf1.y, pf1.y);
                *(float2*)(buf + (kq + 2) * APL2 + pm1 * 2) = make_float2(pf1.z, pf1.z);
                *(float2*)(buf + (kq + 3) * APL2 + pm1 * 2) = make_float2(pf1.w, pf1.w);
            }
            __syncthreads();
            if (c < 7) {
                int ko = (c + 1) * 64 + pk0;
                pf0 = __ldcg((const float4*)(hrow + (size_t)pm0 * H_ + ko));
                pf1 = __ldcg((const float4*)(hrow + (size_t)pm1 * H_ + ko));
            }
            const float* wb = Wgs + (size_t)c * 64 * WGS_LD + tx * 4;
            const float* ab = buf + ty * 4;     // duplicated pair for m-pair
            #pragma unroll 16
            for (int kk = 0; kk < 64; kk++) {
                ulonglong2 ad = *(const ulonglong2*)(ab + kk * APL2);
                ulonglong2 b  = *(const ulonglong2*)(wb + kk * WGS_LD);
                FMA2(a00, ad.x, b.x); FMA2(a01, ad.x, b.y);
                FMA2(a10, ad.y, b.x); FMA2(a11, ad.y, b.y);
            }
        }
        // gate epilogue
        {
            float2 v00 = unpack2(a00), v01 = unpack2(a01);
            float2 v10 = unpack2(a10), v11 = unpack2(a11);
            float4 r0 = make_float4(sigm(v00.x + gx0.x), sigm(v00.y + gx0.y),
                                    sigm(v01.x + gx0.z), sigm(v01.y + gx0.w));
            float4 r1 = make_float4(sigm(v10.x + gx1.x), sigm(v10.y + gx1.y),
                                    sigm(v11.x + gx1.z), sigm(v11.y + gx1.w));
            if (nt < 8) {
                __stcg((float4*)(g_z + m0g * H_ + nbg), r0);
                __stcg((float4*)(g_z + (m0g + 1) * H_ + nbg), r1);
            } else {
                int n2 = nbg - H_;
                r0.x *= hv0.x; r0.y *= hv0.y; r0.z *= hv0.z; r0.w *= hv0.w;
                r1.x *= hv1.x; r1.y *= hv1.y; r1.z *= hv1.z; r1.w *= hv1.w;
                __stcg((float4*)(g_rh + m0g * H_ + n2), r0);
                __stcg((float4*)(g_rh + (m0g + 1) * H_ + n2), r1);
            }
        }
        group_sync(mt, tgt += 16);

        // ===================== CANDIDATE PHASE =====================
        float4 qf0 = __ldcg((const float4*)(rhrow + (size_t)pm0 * H_ + pk0));
        float4 qf1 = __ldcg((const float4*)(rhrow + (size_t)pm1 * H_ + pk0));
        const float* Cxt = g_Cx + (size_t)t * B_ * H_;
        float2 cx0 = __ldcg((const float2*)(Cxt + (size_t)m0g * H_ + nbc));
        float2 cx1 = __ldcg((const float2*)(Cxt + (size_t)(m0g + 1) * H_ + nbc));
        float2 zz0 = __ldcg((const float2*)(g_z + m0g * H_ + nbc));
        float2 zz1 = __ldcg((const float2*)(g_z + (m0g + 1) * H_ + nbc));
        float2 hh0 = __ldcg((const float2*)(g_h + m0g * H_ + nbc));
        float2 hh1 = __ldcg((const float2*)(g_h + (m0g + 1) * H_ + nbc));

        ull c0 = 0ull, c1 = 0ull;
        #pragma unroll 1
        for (int c = 0; c < 8; c++) {
            float* buf = AP + (c & 1) * AP_BUF;
            {
                int kq = pk0;
                *(float2*)(buf + (kq + 0) * APL2 + pm0 * 2) = make_float2(qf0.x, qf0.x);
                *(float2*)(buf + (kq + 1) * APL2 + pm0 * 2) = make_float2(qf0.y, qf0.y);
                *(float2*)(buf + (kq + 2) * APL2 + pm0 * 2) = make_float2(qf0.z, qf0.z);
                *(float2*)(buf + (kq + 3) * APL2 + pm0 * 2) = make_float2(qf0.w, qf0.w);
                *(float2*)(buf + (kq + 0) * APL2 + pm1 * 2) = make_float2(qf1.x, qf1.x);
                *(float2*)(buf + (kq + 1) * APL2 + pm1 * 2) = make_float2(qf1.y, qf1.y);
                *(float2*)(buf + (kq + 2) * APL2 + pm1 * 2) = make_float2(qf1.z, qf1.z);
                *(float2*)(buf + (kq + 3) * APL2 + pm1 * 2) = make_float2(qf1.w, qf1.w);
            }
            __syncthreads();
            if (c < 7) {
                int ko = (c + 1) * 64 + pk0;
                qf0 = __ldcg((const float4*)(rhrow + (size_t)pm0 * H_ + ko));
                qf1 = __ldcg((const float4*)(rhrow + (size_t)pm1 * H_ + ko));
            }
            const float* wb = Whs + (size_t)c * 64 * WHS_LD + tx * 2;
            const float* ab = buf + ty * 4;
            #pragma unroll 16
            for (int kk = 0; kk < 64; kk++) {
                ulonglong2 ad = *(const ulonglong2*)(ab + kk * APL2);
                ull b = *(const ull*)(wb + kk * WHS_LD);
                FMA2(c0, ad.x, b);
                FMA2(c1, ad.y, b);
            }
        }
        // candidate epilogue: h update
        {
            float* hall_t = g_hall + (size_t)t * B_ * H_;
            float2 v0 = unpack2(c0), v1 = unpack2(c1);
            float cnd;
            cnd = tanh_fast(v0.x + cx0.x);
            float h00 = fmaf(zz0.x, cnd - hh0.x, hh0.x);
            cnd = tanh_fast(v0.y + cx0.y);
            float h01 = fmaf(zz0.y, cnd - hh0.y, hh0.y);
            cnd = tanh_fast(v1.x + cx1.x);
            float h10 = fmaf(zz1.x, cnd - hh1.x, hh1.x);
            cnd = tanh_fast(v1.y + cx1.y);
            float h11 = fmaf(zz1.y, cnd - hh1.y, hh1.y);
            float2 w0 = make_float2(h00, h01);
            float2 w1 = make_float2(h10, h11);
            __stcg((float2*)(g_h + m0g * H_ + nbc), w0);
            __stcg((float2*)(g_h + (m0g + 1) * H_ + nbc), w1);
            __stcg((float2*)(hall_t + (size_t)m0g * H_ + nbc), w0);
            __stcg((float2*)(hall_t + (size_t)(m0g + 1) * H_ + nbc), w1);
        }
        group_sync(mt, tgt += 16);
    }
}

// ---------------------------------------------------------------------------
__global__ void gather_embed(const int* __restrict__ x,
                             const float* __restrict__ emb) {
    if (blockIdx.x == 0 && threadIdx.x < 8 * 32)
        g_gcnt[threadIdx.x] = 0;   // reset group-barrier counters each launch
    int idx = blockIdx.x * 256 + threadIdx.x;
    int h4  = idx & (H_ / 4 - 1);
    int row = idx >> 7;
    int b   = row & (B_ - 1);
    int s   = row >> 8;
    int tok = x[b * S_ + s];
    reinterpret_cast<float4*>(g_xe)[(size_t)row * (H_ / 4) + h4] =
        reinterpret_cast<const float4*>(emb)[(size_t)tok * (H_ / 4) + h4];
}

__global__ void copy_hfinal(float* __restrict__ out) {
    int i = blockIdx.x * 256 + threadIdx.x;
    out[i] = g_h[i];
}

// ---------------------------------------------------------------------------
extern "C" void kernel_launch(void* const* d_in, const int* in_sizes, int n_in,
                              void* d_out, int out_size) {
    (void)in_sizes; (void)n_in; (void)out_size;
    const int*   x   = (const int*)  d_in[0];
    const float* emb = (const float*)d_in[1];
    const float* Wg  = (const float*)d_in[2];
    const float* bg  = (const float*)d_in[3];
    const float* Wh  = (const float*)d_in[4];
    const float* bh  = (const float*)d_in[5];
    const float* Wo  = (const float*)d_in[6];
    const float* bo  = (const float*)d_in[7];
    float* out = (float*)d_out;

    static int smem_set = 0;
    if (!smem_set) {
        cudaFuncSetAttribute(gru_persist,
                             cudaFuncAttributeMaxDynamicSharedMemorySize,
                             PERSIST_SMEM);
        smem_set = 1;
    }

    gather_embed<<<(S_ * B_ * (H_ / 4)) / 256, 256>>>(x, emb);

    sgemm_big<<<dim3(H2_ / TBN, (S_ * B_) / TBM), 256>>>(0, Wg, H2_, bg, 0, nullptr);
    sgemm_big<<<dim3(H_  / TBN, (S_ * B_) / TBM), 256>>>(0, Wh, H2_, bh, 1, nullptr);

    gru_persist<<<128, 256, PERSIST_SMEM>>>(Wg, Wh);

    sgemm_big<<<dim3(O_ / TBN, (S_ * B_) / TBM), 256>>>(1, Wo, H_, bo, 2,
                                                        out + (size_t)B_ * H_);
    copy_hfinal<<<(B_ * H_) / 256, 256>>>(out);
}

// round 10
// speedup vs baseline: 1.6993x; 1.6993x over previous
#include <cuda_runtime.h>
#include <math.h>
#include <stdint.h>

// Problem constants
#define B_  256
#define S_  256
#define H_  512
#define H2_ 1024
#define O_  512

typedef unsigned long long ull;

// ---------------------------------------------------------------------------
// Scratch (device globals)
// ---------------------------------------------------------------------------
__device__ float g_xe  [(size_t)S_ * B_ * H_ ];
__device__ float g_Gx  [(size_t)S_ * B_ * H2_];
__device__ float g_Cx  [(size_t)S_ * B_ * H_ ];
__device__ float g_hall[(size_t)S_ * B_ * H_ ];
__device__ float g_h   [B_ * H_];
__device__ float g_z   [B_ * H_];
__device__ float g_rh  [B_ * H_];

__device__ unsigned g_gcnt[8 * 32];   // group barrier counters (128B apart)

// ---------------------------------------------------------------------------
// f32x2 helpers (big GEMM only)
// ---------------------------------------------------------------------------
#define FMA2(d, a, b) \
    asm("fma.rn.f32x2 %0, %1, %2, %3;" : "=l"(d) : "l"(a), "l"(b), "l"(d))

__device__ __forceinline__ ull splat2(float x) {
    ull d;
    asm("mov.b64 %0, {%1, %1};" : "=l"(d) : "r"(__float_as_uint(x)));
    return d;
}
__device__ __forceinline__ float2 unpack2(ull v) {
    float2 r;
    asm("mov.b64 {%0, %1}, %2;" : "=f"(r.x), "=f"(r.y) : "l"(v));
    return r;
}
__device__ __forceinline__ float sigm(float x) {
    return __fdividef(1.0f, 1.0f + __expf(-x));
}
__device__ __forceinline__ float tanh_fast(float x) {
    return 1.0f - 2.0f * __fdividef(1.0f, __expf(2.0f * x) + 1.0f);
}

// ---------------------------------------------------------------------------
// Group barrier (16 blocks/group): REDG arrival + monotonic count wait
// ---------------------------------------------------------------------------
__device__ __forceinline__ void group_sync(int grp, unsigned target) {
    __threadfence();
    __syncthreads();
    if (threadIdx.x == 0) {
        unsigned* cp = &g_gcnt[grp * 32];
        asm volatile("red.global.gpu.add.u32 [%0], %1;"
                     :: "l"(cp), "r"(1u) : "memory");
        unsigned v;
        do {
            asm volatile("ld.acquire.gpu.u32 %0, [%1];" : "=r"(v) : "l"(cp));
        } while (v < target);
    }
    __syncthreads();
}

// ---------------------------------------------------------------------------
// bf16 split + mma.sync (baseline PTX, no arch-feature suffix needed)
// ---------------------------------------------------------------------------
// pack (f0,f1) -> bf16x2 hi word {lo=f0, hi=f1}; lo word = residuals
__device__ __forceinline__ void cvt_pair(float f0, float f1,
                                         unsigned& hi2, unsigned& lo2) {
    asm("cvt.rn.bf16x2.f32 %0, %2, %1;" : "=r"(hi2) : "f"(f0), "f"(f1));
    float h0 = __uint_as_float(hi2 << 16);
    float h1 = __uint_as_float(hi2 & 0xFFFF0000u);
    float l0 = f0 - h0, l1 = f1 - h1;
    asm("cvt.rn.bf16x2.f32 %0, %2, %1;" : "=r"(lo2) : "f"(l0), "f"(l1));
}

__device__ __forceinline__ void mma16816(float* c,
                                         unsigned a0, unsigned a1,
                                         unsigned a2, unsigned a3,
                                         unsigned b0, unsigned b1) {
    asm volatile(
        "mma.sync.aligned.m16n8k16.row.col.f32.bf16.bf16.f32 "
        "{%0,%1,%2,%3}, {%4,%5,%6,%7}, {%8,%9}, {%0,%1,%2,%3};"
        : "+f"(c[0]), "+f"(c[1]), "+f"(c[2]), "+f"(c[3])
        : "r"(a0), "r"(a1), "r"(a2), "r"(a3), "r"(b0), "r"(b1));
}

// ---------------------------------------------------------------------------
// Big SGEMM (proven, unchanged): C[M,N] = A[M,512] @ Bw[N,512]^T + bias
// ---------------------------------------------------------------------------
#define TBM 128
#define TBN 128
#define TBK 16
#define LDT 132

__global__ __launch_bounds__(256, 2)
void sgemm_big(int Asel, const float* __restrict__ Bw, int ldb,
               const float* __restrict__ bias, int mode,
               float* __restrict__ yout) {
    __shared__ float As[TBK * LDT];
    __shared__ float Bs[TBK * LDT];

    const int tid = threadIdx.x;
    const int ty  = tid >> 4;
    const int tx  = tid & 15;
    const int m0  = blockIdx.y * TBM;
    const int n0  = blockIdx.x * TBN;

    const float* A = Asel ? g_hall : g_xe;

    ull acc[4][8];
    #pragma unroll
    for (int i = 0; i < 4; i++)
        #pragma unroll
        for (int j = 0; j < 8; j++) acc[i][j] = 0ull;

    for (int k0 = 0; k0 < H_; k0 += TBK) {
        #pragma unroll
        for (int it = 0; it < 2; it++) {
            int idx = tid + it * 256;
            int r   = idx >> 2;
            int kq  = idx & 3;
            float4 av = *(const float4*)(A  + (size_t)(m0 + r) * H_ + k0 + kq * 4);
            float4 bv = *(const float4*)(Bw + (size_t)(n0 + r) * ldb + k0 + kq * 4);
            As[(kq * 4 + 0) * LDT + r] = av.x;
            As[(kq * 4 + 1) * LDT + r] = av.y;
            As[(kq * 4 + 2) * LDT + r] = av.z;
            As[(kq * 4 + 3) * LDT + r] = av.w;
            Bs[(kq * 4 + 0) * LDT + r] = bv.x;
            Bs[(kq * 4 + 1) * LDT + r] = bv.y;
            Bs[(kq * 4 + 2) * LDT + r] = bv.z;
            Bs[(kq * 4 + 3) * LDT + r] = bv.w;
        }
        __syncthreads();

        #pragma unroll
        for (int kk = 0; kk < TBK; kk++) {
            ulonglong2 a01 = *(const ulonglong2*)&As[kk * LDT + ty * 8];
            ulonglong2 a23 = *(const ulonglong2*)&As[kk * LDT + ty * 8 + 4];
            float4 bl  = *(const float4*)&Bs[kk * LDT + tx * 8];
            float4 bh4 = *(const float4*)&Bs[kk * LDT + tx * 8 + 4];
            ull ap[4] = {a01.x, a01.y, a23.x, a23.y};
            float bsc[8] = {bl.x, bl.y, bl.z, bl.w, bh4.x, bh4.y, bh4.z, bh4.w};
            #pragma unroll
            for (int j = 0; j < 8; j++) {
                ull bb = splat2(bsc[j]);
                #pragma unroll
                for (int i = 0; i < 4; i++) FMA2(acc[i][j], ap[i], bb);
            }
        }
        __syncthreads();
    }

    #pragma unroll
    for (int i = 0; i < 4; i++) {
        #pragma unroll
        for (int j = 0; j < 8; j++) {
            float2 v = unpack2(acc[i][j]);
            int n  = n0 + tx * 8 + j;
            float bval = bias[n];
            int mA = m0 + ty * 8 + i * 2;
            int mB = mA + 1;
            float oA = v.x + bval, oB = v.y + bval;
            if (mode == 0) {
                g_Gx[(size_t)mA * H2_ + n] = oA;
                g_Gx[(size_t)mB * H2_ + n] = oB;
            } else if (mode == 1) {
                g_Cx[(size_t)mA * H_ + n] = oA;
                g_Cx[(size_t)mB * H_ + n] = oB;
            } else {
                int sA = mA >> 8, bA = mA & 255;
                int sB = mB >> 8, bB = mB & 255;
                yout[((size_t)bA * S_ + sA) * O_ + n] = oA;
                yout[((size_t)bB * S_ + sB) * O_ + n] = oB;
            }
        }
    }
}

// ---------------------------------------------------------------------------
// mma.sync persistent recurrent kernel: 128 blocks x 256 threads (8 warps).
// Block (mt=bid>>4, nt=bid&15), group barrier over the 16-block mt-group.
//   gate: m [mt*32,+32) x n [nt*64,+64) of 1024; warp = m16 x n16 (2 b-tiles)
//   cand: m [mt*32,+32) x n [nt*32,+32) of 512;  warp = m16 x n8
// Weights pre-split to bf16 hi/lo in smem ([n][k], 1040B stride).
// A (h/rh) split per 128-k chunk into 32x128 bf16 hi/lo panel (272B stride),
// next chunk prefetched into registers during the mma mainloop.
// Split-3 products: hi*hi + hi*lo + lo*hi  (error ~1e-5).
// ---------------------------------------------------------------------------
#define WROW 1040                       // weight smem row stride (bytes)
#define AROW 272                        // A-panel row stride (bytes)
#define SM_WGH 0
#define SM_WGL (SM_WGH + 64 * WROW)     // 66560
#define SM_WHH (SM_WGL + 64 * WROW)     // 133120
#define SM_WHL (SM_WHH + 32 * WROW)     // 166400
#define SM_AH  (SM_WHL + 32 * WROW)     // 199680
#define SM_AL  (SM_AH + 32 * AROW)      // 208384
#define GRU_SMEM (SM_AL + 32 * AROW)    // 217088 bytes

__global__ __launch_bounds__(256, 1)
void gru_persist(const float* __restrict__ Wg, const float* __restrict__ Wh) {
    extern __shared__ char smc[];

    const int tid  = threadIdx.x;
    const int bid  = blockIdx.x;
    const int mt   = bid >> 4;          // 0..7
    const int nt   = bid & 15;          // 0..15
    const int wid  = tid >> 5;          // 0..7
    const int lane = tid & 31;
    const int wm   = wid >> 2;          // 0..1  (m half)
    const int wn   = wid & 3;           // 0..3  (n quarter)
    const int g    = lane >> 2;         // 0..7
    const int tg   = lane & 3;          // 0..3

    // zero h
    {
        int base = (bid * 256 + tid) * 4;
        *(float4*)&g_h[base] = make_float4(0.f, 0.f, 0.f, 0.f);
    }

    // ---- pre-split weights into smem bf16 hi/lo ----
    {   // Wg: 64 rows (nt*64+j), k in [512,1024)
        int j  = tid >> 2;
        int ks = (tid & 3) * 128;
        const float* src = Wg + (size_t)(nt * 64 + j) * H2_ + H_ + ks;
        char* dh = smc + SM_WGH + j * WROW + ks * 2;
        char* dl = smc + SM_WGL + j * WROW + ks * 2;
        #pragma unroll 8
        for (int q = 0; q < 32; q++) {
            float4 v = *(const float4*)(src + q * 4);
            unsigned h0, l0, h1, l1;
            cvt_pair(v.x, v.y, h0, l0);
            cvt_pair(v.z, v.w, h1, l1);
            *(uint2*)(dh + q * 8) = make_uint2(h0, h1);
            *(uint2*)(dl + q * 8) = make_uint2(l0, l1);
        }
    }
    {   // Wh: 32 rows (nt*32+j), k in [512,1024)
        int j  = tid >> 3;
        int ks = (tid & 7) * 64;
        const float* src = Wh + (size_t)(nt * 32 + j) * H2_ + H_ + ks;
        char* dh = smc + SM_WHH + j * WROW + ks * 2;
        char* dl = smc + SM_WHL + j * WROW + ks * 2;
        #pragma unroll 8
        for (int q = 0; q < 16; q++) {
            float4 v = *(const float4*)(src + q * 4);
            unsigned h0, l0, h1, l1;
            cvt_pair(v.x, v.y, h0, l0);
            cvt_pair(v.z, v.w, h1, l1);
            *(uint2*)(dh + q * 8) = make_uint2(h0, h1);
            *(uint2*)(dl + q * 8) = make_uint2(l0, l1);
        }
    }
    unsigned tgt = 0;
    group_sync(mt, tgt += 16);

    const float* hrow  = g_h  + (size_t)mt * 32 * H_;
    const float* rhrow = g_rh + (size_t)mt * 32 * H_;

    // A-panel convert coords: row pr, k-seg pks (16 k per thread per quarter)
    const int pr  = tid >> 3;            // 0..31
    const int pks = (tid & 7) * 16;      // 0..112

    // fragment base offsets (bytes)
    const int aHb = SM_AH + (wm * 16 + g) * AROW + tg * 4;
    const int aLb = SM_AL + (wm * 16 + g) * AROW + tg * 4;
    const int bgH0 = SM_WGH + (wn * 16 + g) * WROW + tg * 4;
    const int bgH1 = SM_WGH + (wn * 16 + 8 + g) * WROW + tg * 4;
    const int bgL0 = SM_WGL + (wn * 16 + g) * WROW + tg * 4;
    const int bgL1 = SM_WGL + (wn * 16 + 8 + g) * WROW + tg * 4;
    const int bhH  = SM_WHH + (wn * 8 + g) * WROW + tg * 4;
    const int bhL  = SM_WHL + (wn * 8 + g) * WROW + tg * 4;

    const int r0 = mt * 32 + wm * 16 + g;       // output rows r0, r0+8

    for (int t = 0; t < S_; t++) {
        // ===================== GATE PHASE =====================
        float cg0[4] = {0.f, 0.f, 0.f, 0.f};
        float cg1[4] = {0.f, 0.f, 0.f, 0.f};
        float4 pf[4];
        #pragma unroll
        for (int q = 0; q < 4; q++)
            pf[q] = __ldcg((const float4*)(hrow + (size_t)pr * H_ + pks + q * 4));

        #pragma unroll 1
        for (int c = 0; c < 4; c++) {
            // convert + store this chunk's panel
            {
                char* dh = smc + SM_AH + pr * AROW + pks * 2;
                char* dl = smc + SM_AL + pr * AROW + pks * 2;
                #pragma unroll
                for (int q = 0; q < 4; q++) {
                    unsigned h0, l0, h1, l1;
                    cvt_pair(pf[q].x, pf[q].y, h0, l0);
                    cvt_pair(pf[q].z, pf[q].w, h1, l1);
                    *(uint2*)(dh + q * 8) = make_uint2(h0, h1);
                    *(uint2*)(dl + q * 8) = make_uint2(l0, l1);
                }
            }
            __syncthreads();
            if (c < 3) {
                #pragma unroll
                for (int q = 0; q < 4; q++)
                    pf[q] = __ldcg((const float4*)(hrow + (size_t)pr * H_
                                                   + (c + 1) * 128 + pks + q * 4));
            }
            const int kwb = c * 256;     // weight k byte base for this chunk
            #pragma unroll
            for (int s = 0; s < 8; s++) {
                const int ka = s * 32;           // A k byte off
                const int kw = kwb + s * 32;     // W k byte off
                unsigned aH0 = *(const unsigned*)(smc + aHb + ka);
                unsigned aH1 = *(const unsigned*)(smc + aHb + 8 * AROW + ka);
                unsigned aH2 = *(const unsigned*)(smc + aHb + ka + 16);
                unsigned aH3 = *(const unsigned*)(smc + aHb + 8 * AROW + ka + 16);
                unsigned aL0 = *(const unsigned*)(smc + aLb + ka);
                unsigned aL1 = *(const unsigned*)(smc + aLb + 8 * AROW + ka);
                unsigned aL2 = *(const unsigned*)(smc + aLb + ka + 16);
                unsigned aL3 = *(const unsigned*)(smc + aLb + 8 * AROW + ka + 16);
                unsigned b0h0 = *(const unsigned*)(smc + bgH0 + kw);
                unsigned b0h1 = *(const unsigned*)(smc + bgH0 + kw + 16);
                unsigned b0l0 = *(const unsigned*)(smc + bgL0 + kw);
                unsigned b0l1 = *(const unsigned*)(smc + bgL0 + kw + 16);
                unsigned b1h0 = *(const unsigned*)(smc + bgH1 + kw);
                unsigned b1h1 = *(const unsigned*)(smc + bgH1 + kw + 16);
                unsigned b1l0 = *(const unsigned*)(smc + bgL1 + kw);
                unsigned b1l1 = *(const unsigned*)(smc + bgL1 + kw + 16);
                mma16816(cg0, aH0, aH1, aH2, aH3, b0h0, b0h1);
                mma16816(cg0, aH0, aH1, aH2, aH3, b0l0, b0l1);
                mma16816(cg0, aL0, aL1, aL2, aL3, b0h0, b0h1);
                mma16816(cg1, aH0, aH1, aH2, aH3, b1h0, b1h1);
                mma16816(cg1, aH0, aH1, aH2, aH3, b1l0, b1l1);
                mma16816(cg1, aL0, aL1, aL2, aL3, b1h0, b1h1);
            }
            if (c < 3) __syncthreads();
        }
        // gate epilogue
        {
            const float* Gxt = g_Gx + (size_t)t * B_ * H2_;
            #pragma unroll
            for (int tile = 0; tile < 2; tile++) {
                float* cc = tile ? cg1 : cg0;
                int n = nt * 64 + wn * 16 + tile * 8 + tg * 2;
                float2 gx0 = __ldcg((const float2*)(Gxt + (size_t)r0 * H2_ + n));
                float2 gx1 = __ldcg((const float2*)(Gxt + (size_t)(r0 + 8) * H2_ + n));
                float v00 = sigm(cc[0] + gx0.x), v01 = sigm(cc[1] + gx0.y);
                float v10 = sigm(cc[2] + gx1.x), v11 = sigm(cc[3] + gx1.y);
                if (nt < 8) {
                    __stcg((float2*)(g_z + r0 * H_ + n), make_float2(v00, v01));
                    __stcg((float2*)(g_z + (r0 + 8) * H_ + n), make_float2(v10, v11));
                } else {
                    int n2 = n - H_;
                    float2 hv0 = __ldcg((const float2*)(g_h + r0 * H_ + n2));
                    float2 hv1 = __ldcg((const float2*)(g_h + (r0 + 8) * H_ + n2));
                    __stcg((float2*)(g_rh + r0 * H_ + n2),
                           make_float2(v00 * hv0.x, v01 * hv0.y));
                    __stcg((float2*)(g_rh + (r0 + 8) * H_ + n2),
                           make_float2(v10 * hv1.x, v11 * hv1.y));
                }
            }
        }
        group_sync(mt, tgt += 16);

        // ===================== CANDIDATE PHASE =====================
        float cc[4] = {0.f, 0.f, 0.f, 0.f};
        #pragma unroll
        for (int q = 0; q < 4; q++)
            pf[q] = __ldcg((const float4*)(rhrow + (size_t)pr * H_ + pks + q * 4));

        #pragma unroll 1
        for (int c = 0; c < 4; c++) {
            {
                char* dh = smc + SM_AH + pr * AROW + pks * 2;
                char* dl = smc + SM_AL + pr * AROW + pks * 2;
                #pragma unroll
                for (int q = 0; q < 4; q++) {
                    unsigned h0, l0, h1, l1;
                    cvt_pair(pf[q].x, pf[q].y, h0, l0);
                    cvt_pair(pf[q].z, pf[q].w, h1, l1);
                    *(uint2*)(dh + q * 8) = make_uint2(h0, h1);
                    *(uint2*)(dl + q * 8) = make_uint2(l0, l1);
                }
            }
            __syncthreads();
            if (c < 3) {
                #pragma unroll
                for (int q = 0; q < 4; q++)
                    pf[q] = __ldcg((const float4*)(rhrow + (size_t)pr * H_
                                                   + (c + 1) * 128 + pks + q * 4));
            }
            const int kwb = c * 256;
            #pragma unroll
            for (int s = 0; s < 8; s++) {
                const int ka = s * 32;
                const int kw = kwb + s * 32;
                unsigned aH0 = *(const unsigned*)(smc + aHb + ka);
                unsigned aH1 = *(const unsigned*)(smc + aHb + 8 * AROW + ka);
                unsigned aH2 = *(const unsigned*)(smc + aHb + ka + 16);
                unsigned aH3 = *(const unsigned*)(smc + aHb + 8 * AROW + ka + 16);
                unsigned aL0 = *(const unsigned*)(smc + aLb + ka);
                unsigned aL1 = *(const unsigned*)(smc + aLb + 8 * AROW + ka);
                unsigned aL2 = *(const unsigned*)(smc + aLb + ka + 16);
                unsigned aL3 = *(const unsigned*)(smc + aLb + 8 * AROW + ka + 16);
                unsigned bh0 = *(const unsigned*)(smc + bhH + kw);
                unsigned bh1 = *(const unsigned*)(smc + bhH + kw + 16);
                unsigned bl0 = *(const unsigned*)(smc + bhL + kw);
                unsigned bl1 = *(const unsigned*)(smc + bhL + kw + 16);
                mma16816(cc, aH0, aH1, aH2, aH3, bh0, bh1);
                mma16816(cc, aH0, aH1, aH2, aH3, bl0, bl1);
                mma16816(cc, aL0, aL1, aL2, aL3, bh0, bh1);
            }
            if (c < 3) __syncthreads();
        }
        // candidate epilogue: h update
        {
            float* hall_t = g_hall + (size_t)t * B_ * H_;
            const float* Cxt = g_Cx + (size_t)t * B_ * H_;
            int n = nt * 32 + wn * 8 + tg * 2;
            #pragma unroll
            for (int rr = 0; rr < 2; rr++) {
                int r = r0 + rr * 8;
                size_t idx = (size_t)r * H_ + n;
                float2 cx = __ldcg((const float2*)(Cxt + idx));
                float2 zz = __ldcg((const float2*)(g_z + idx));
                float2 hh = __ldcg((const float2*)(g_h + idx));
                float c0 = tanh_fast(cc[rr * 2 + 0] + cx.x);
                float c1 = tanh_fast(cc[rr * 2 + 1] + cx.y);
                float2 hn = make_float2(fmaf(zz.x, c0 - hh.x, hh.x),
                                        fmaf(zz.y, c1 - hh.y, hh.y));
                __stcg((float2*)(g_h + idx), hn);
                __stcg((float2*)(hall_t + idx), hn);
            }
        }
        group_sync(mt, tgt += 16);
    }
}

// ---------------------------------------------------------------------------
__global__ void gather_embed(const int* __restrict__ x,
                             const float* __restrict__ emb) {
    if (blockIdx.x == 0 && threadIdx.x < 8 * 32)
        g_gcnt[threadIdx.x] = 0;   // reset group-barrier counters each launch
    int idx = blockIdx.x * 256 + threadIdx.x;
    int h4  = idx & (H_ / 4 - 1);
    int row = idx >> 7;
    int b   = row & (B_ - 1);
    int s   = row >> 8;
    int tok = x[b * S_ + s];
    reinterpret_cast<float4*>(g_xe)[(size_t)row * (H_ / 4) + h4] =
        reinterpret_cast<const float4*>(emb)[(size_t)tok * (H_ / 4) + h4];
}

__global__ void copy_hfinal(float* __restrict__ out) {
    int i = blockIdx.x * 256 + threadIdx.x;
    out[i] = g_h[i];
}

// ---------------------------------------------------------------------------
extern "C" void kernel_launch(void* const* d_in, const int* in_sizes, int n_in,
                              void* d_out, int out_size) {
    (void)in_sizes; (void)n_in; (void)out_size;
    const int*   x   = (const int*)  d_in[0];
    const float* emb = (const float*)d_in[1];
    const float* Wg  = (const float*)d_in[2];
    const float* bg  = (const float*)d_in[3];
    const float* Wh  = (const float*)d_in[4];
    const float* bh  = (const float*)d_in[5];
    const float* Wo  = (const float*)d_in[6];
    const float* bo  = (const float*)d_in[7];
    float* out = (float*)d_out;

    static int smem_set = 0;
    if (!smem_set) {
        cudaFuncSetAttribute(gru_persist,
                             cudaFuncAttributeMaxDynamicSharedMemorySize,
                             GRU_SMEM);
        smem_set = 1;
    }

    gather_embed<<<(S_ * B_ * (H_ / 4)) / 256, 256>>>(x, emb);

    sgemm_big<<<dim3(H2_ / TBN, (S_ * B_) / TBM), 256>>>(0, Wg, H2_, bg, 0, nullptr);
    sgemm_big<<<dim3(H_  / TBN, (S_ * B_) / TBM), 256>>>(0, Wh, H2_, bh, 1, nullptr);

    gru_persist<<<128, 256, GRU_SMEM>>>(Wg, Wh);

    sgemm_big<<<dim3(O_ / TBN, (S_ * B_) / TBM), 256>>>(1, Wo, H_, bo, 2,
                                                        out + (size_t)B_ * H_);
    copy_hfinal<<<(B_ * H_) / 256, 256>>>(out);
}

// round 11
// speedup vs baseline: 2.3430x; 1.3788x over previous
#include <cuda_runtime.h>
#include <math.h>
#include <stdint.h>

// Problem constants
#define B_  256
#define S_  256
#define H_  512
#define H2_ 1024
#define O_  512

typedef unsigned long long ull;

// ---------------------------------------------------------------------------
// Scratch (device globals)
// ---------------------------------------------------------------------------
__device__ float g_xe  [(size_t)S_ * B_ * H_ ];
__device__ float g_Gx  [(size_t)S_ * B_ * H2_];
__device__ float g_Cx  [(size_t)S_ * B_ * H_ ];
__device__ float g_hall[(size_t)S_ * B_ * H_ ];
__device__ float g_h   [B_ * H_];
__device__ float g_z   [B_ * H_];
__device__ float g_rh  [B_ * H_];

__device__ unsigned g_gcnt[8 * 32];   // group barrier counters (128B apart)

// ---------------------------------------------------------------------------
// helpers
// ---------------------------------------------------------------------------
__device__ __forceinline__ float sigm(float x) {
    return __fdividef(1.0f, 1.0f + __expf(-x));
}
__device__ __forceinline__ float tanh_fast(float x) {
    return 1.0f - 2.0f * __fdividef(1.0f, __expf(2.0f * x) + 1.0f);
}

// pack (f0,f1) -> bf16x2 hi word {lo=f0, hi=f1}; lo word = residuals
__device__ __forceinline__ void cvt_pair(float f0, float f1,
                                         unsigned& hi2, unsigned& lo2) {
    asm("cvt.rn.bf16x2.f32 %0, %2, %1;" : "=r"(hi2) : "f"(f0), "f"(f1));
    float h0 = __uint_as_float(hi2 << 16);
    float h1 = __uint_as_float(hi2 & 0xFFFF0000u);
    float l0 = f0 - h0, l1 = f1 - h1;
    asm("cvt.rn.bf16x2.f32 %0, %2, %1;" : "=r"(lo2) : "f"(l0), "f"(l1));
}

__device__ __forceinline__ void mma16816(float* c,
                                         unsigned a0, unsigned a1,
                                         unsigned a2, unsigned a3,
                                         unsigned b0, unsigned b1) {
    asm volatile(
        "mma.sync.aligned.m16n8k16.row.col.f32.bf16.bf16.f32 "
        "{%0,%1,%2,%3}, {%4,%5,%6,%7}, {%8,%9}, {%0,%1,%2,%3};"
        : "+f"(c[0]), "+f"(c[1]), "+f"(c[2]), "+f"(c[3])
        : "r"(a0), "r"(a1), "r"(a2), "r"(a3), "r"(b0), "r"(b1));
}

// ---------------------------------------------------------------------------
// Group barrier (16 blocks/group): REDG arrival + monotonic count wait
// ---------------------------------------------------------------------------
__device__ __forceinline__ void group_sync(int grp, unsigned target) {
    __threadfence();
    __syncthreads();
    if (threadIdx.x == 0) {
        unsigned* cp = &g_gcnt[grp * 32];
        asm volatile("red.global.gpu.add.u32 [%0], %1;"
                     :: "l"(cp), "r"(1u) : "memory");
        unsigned v;
        do {
            asm volatile("ld.acquire.gpu.u32 %0, [%1];" : "=r"(v) : "l"(cp));
        } while (v < target);
    }
    __syncthreads();
}

// ---------------------------------------------------------------------------
// Tensor-core big GEMM: C[65536, N] = A[65536,512] @ Bw[N,512]^T + bias
// 128x128 block, 8 warps (warp = 32m x 64n), bf16-split x3 mma.sync.
// A/B tiles (128x16 fp32) converted to bf16 hi/lo in smem each k-iter.
// ---------------------------------------------------------------------------
#define ASTR 48   // smem row stride bytes (16 bf16 = 32B data + 16B pad)

__global__ __launch_bounds__(256, 2)
void sgemm_tc(int Asel, const float* __restrict__ Bw, int ldb,
              const float* __restrict__ bias, int mode,
              float* __restrict__ yout) {
    __shared__ char sAH[128 * ASTR];
    __shared__ char sAL[128 * ASTR];
    __shared__ char sBH[128 * ASTR];
    __shared__ char sBL[128 * ASTR];

    const int tid  = threadIdx.x;
    const int wid  = tid >> 5;
    const int lane = tid & 31;
    const int g    = lane >> 2;
    const int tg   = lane & 3;
    const int wm   = wid >> 1;          // 0..3 -> m offset wm*32
    const int wn   = wid & 1;           // 0..1 -> n offset wn*64
    const int m0   = blockIdx.y * 128;
    const int n0   = blockIdx.x * 128;

    const float* A = Asel ? g_hall : g_xe;
    const int lr = tid >> 1;            // 0..127 load row
    const int lh = tid & 1;             // k half (8 floats)
    const float* Ap = A  + (size_t)(m0 + lr) * H_  + lh * 8;
    const float* Bp = Bw + (size_t)(n0 + lr) * ldb + lh * 8;

    float c[2][8][4];
    #pragma unroll
    for (int i = 0; i < 2; i++)
        #pragma unroll
        for (int j = 0; j < 8; j++)
            #pragma unroll
            for (int q = 0; q < 4; q++) c[i][j][q] = 0.f;

    float4 pa0 = *(const float4*)(Ap);
    float4 pa1 = *(const float4*)(Ap + 4);
    float4 pb0 = *(const float4*)(Bp);
    float4 pb1 = *(const float4*)(Bp + 4);

    #pragma unroll 1
    for (int k0 = 0; k0 < H_; k0 += 16) {
        {   // convert + store tiles
            unsigned h0, l0, h1, l1, h2, l2, h3, l3;
            cvt_pair(pa0.x, pa0.y, h0, l0); cvt_pair(pa0.z, pa0.w, h1, l1);
            cvt_pair(pa1.x, pa1.y, h2, l2); cvt_pair(pa1.z, pa1.w, h3, l3);
            char* dA = (char*)(lr * ASTR + lh * 16);
            *(uint2*)(sAH + (size_t)dA)     = make_uint2(h0, h1);
            *(uint2*)(sAH + (size_t)dA + 8) = make_uint2(h2, h3);
            *(uint2*)(sAL + (size_t)dA)     = make_uint2(l0, l1);
            *(uint2*)(sAL + (size_t)dA + 8) = make_uint2(l2, l3);
            cvt_pair(pb0.x, pb0.y, h0, l0); cvt_pair(pb0.z, pb0.w, h1, l1);
            cvt_pair(pb1.x, pb1.y, h2, l2); cvt_pair(pb1.z, pb1.w, h3, l3);
            *(uint2*)(sBH + (size_t)dA)     = make_uint2(h0, h1);
            *(uint2*)(sBH + (size_t)dA + 8) = make_uint2(h2, h3);
            *(uint2*)(sBL + (size_t)dA)     = make_uint2(l0, l1);
            *(uint2*)(sBL + (size_t)dA + 8) = make_uint2(l2, l3);
        }
        __syncthreads();
        if (k0 < H_ - 16) {
            pa0 = *(const float4*)(Ap + k0 + 16);
            pa1 = *(const float4*)(Ap + k0 + 20);
            pb0 = *(const float4*)(Bp + k0 + 16);
            pb1 = *(const float4*)(Bp + k0 + 20);
        }
        // A fragments (2 m16 tiles, hi+lo)
        unsigned aH[2][4], aL[2][4];
        #pragma unroll
        for (int mt = 0; mt < 2; mt++) {
            int ab = (wm * 32 + mt * 16 + g) * ASTR + tg * 4;
            aH[mt][0] = *(const unsigned*)(sAH + ab);
            aH[mt][1] = *(const unsigned*)(sAH + ab + 8 * ASTR);
            aH[mt][2] = *(const unsigned*)(sAH + ab + 16);
            aH[mt][3] = *(const unsigned*)(sAH + ab + 8 * ASTR + 16);
            aL[mt][0] = *(const unsigned*)(sAL + ab);
            aL[mt][1] = *(const unsigned*)(sAL + ab + 8 * ASTR);
            aL[mt][2] = *(const unsigned*)(sAL + ab + 16);
            aL[mt][3] = *(const unsigned*)(sAL + ab + 8 * ASTR + 16);
        }
        #pragma unroll
        for (int nt2 = 0; nt2 < 8; nt2++) {
            int nb = (wn * 64 + nt2 * 8 + g) * ASTR + tg * 4;
            unsigned bh0 = *(const unsigned*)(sBH + nb);
            unsigned bh1 = *(const unsigned*)(sBH + nb + 16);
            unsigned bl0 = *(const unsigned*)(sBL + nb);
            unsigned bl1 = *(const unsigned*)(sBL + nb + 16);
            #pragma unroll
            for (int mt = 0; mt < 2; mt++) {
                mma16816(c[mt][nt2], aH[mt][0], aH[mt][1], aH[mt][2], aH[mt][3], bh0, bh1);
                mma16816(c[mt][nt2], aH[mt][0], aH[mt][1], aH[mt][2], aH[mt][3], bl0, bl1);
                mma16816(c[mt][nt2], aL[mt][0], aL[mt][1], aL[mt][2], aL[mt][3], bh0, bh1);
            }
        }
        __syncthreads();
    }

    // epilogue
    #pragma unroll
    for (int mt = 0; mt < 2; mt++) {
        int row0 = m0 + wm * 32 + mt * 16 + g;
        int row1 = row0 + 8;
        #pragma unroll
        for (int nt2 = 0; nt2 < 8; nt2++) {
            int n = n0 + wn * 64 + nt2 * 8 + tg * 2;
            float2 bv = *(const float2*)(bias + n);
            float o00 = c[mt][nt2][0] + bv.x, o01 = c[mt][nt2][1] + bv.y;
            float o10 = c[mt][nt2][2] + bv.x, o11 = c[mt][nt2][3] + bv.y;
            if (mode == 0) {
                *(float2*)(g_Gx + (size_t)row0 * H2_ + n) = make_float2(o00, o01);
                *(float2*)(g_Gx + (size_t)row1 * H2_ + n) = make_float2(o10, o11);
            } else if (mode == 1) {
                *(float2*)(g_Cx + (size_t)row0 * H_ + n) = make_float2(o00, o01);
                *(float2*)(g_Cx + (size_t)row1 * H_ + n) = make_float2(o10, o11);
            } else {
                int s0 = row0 >> 8, b0i = row0 & 255;
                int s1 = row1 >> 8, b1i = row1 & 255;
                *(float2*)(yout + ((size_t)b0i * S_ + s0) * O_ + n) = make_float2(o00, o01);
                *(float2*)(yout + ((size_t)b1i * S_ + s1) * O_ + n) = make_float2(o10, o11);
            }
        }
    }
}

// ---------------------------------------------------------------------------
// mma.sync persistent recurrent kernel (UNCHANGED from R10, proven 3.65ms):
// 128 blocks x 256 threads (8 warps), group-of-16 barriers.
// ---------------------------------------------------------------------------
#define WROW 1040
#define AROW 272
#define SM_WGH 0
#define SM_WGL (SM_WGH + 64 * WROW)
#define SM_WHH (SM_WGL + 64 * WROW)
#define SM_WHL (SM_WHH + 32 * WROW)
#define SM_AH  (SM_WHL + 32 * WROW)
#define SM_AL  (SM_AH + 32 * AROW)
#define GRU_SMEM (SM_AL + 32 * AROW)    // 217088 bytes

__global__ __launch_bounds__(256, 1)
void gru_persist(const float* __restrict__ Wg, const float* __restrict__ Wh) {
    extern __shared__ char smc[];

    const int tid  = threadIdx.x;
    const int bid  = blockIdx.x;
    const int mt   = bid >> 4;
    const int nt   = bid & 15;
    const int wid  = tid >> 5;
    const int lane = tid & 31;
    const int wm   = wid >> 2;
    const int wn   = wid & 3;
    const int g    = lane >> 2;
    const int tg   = lane & 3;

    {
        int base = (bid * 256 + tid) * 4;
        *(float4*)&g_h[base] = make_float4(0.f, 0.f, 0.f, 0.f);
    }

    {   // Wg: 64 rows (nt*64+j), k in [512,1024)
        int j  = tid >> 2;
        int ks = (tid & 3) * 128;
        const float* src = Wg + (size_t)(nt * 64 + j) * H2_ + H_ + ks;
        char* dh = smc + SM_WGH + j * WROW + ks * 2;
        char* dl = smc + SM_WGL + j * WROW + ks * 2;
        #pragma unroll 8
        for (int q = 0; q < 32; q++) {
            float4 v = *(const float4*)(src + q * 4);
            unsigned h0, l0, h1, l1;
            cvt_pair(v.x, v.y, h0, l0);
            cvt_pair(v.z, v.w, h1, l1);
            *(uint2*)(dh + q * 8) = make_uint2(h0, h1);
            *(uint2*)(dl + q * 8) = make_uint2(l0, l1);
        }
    }
    {   // Wh: 32 rows (nt*32+j), k in [512,1024)
        int j  = tid >> 3;
        int ks = (tid & 7) * 64;
        const float* src = Wh + (size_t)(nt * 32 + j) * H2_ + H_ + ks;
        char* dh = smc + SM_WHH + j * WROW + ks * 2;
        char* dl = smc + SM_WHL + j * WROW + ks * 2;
        #pragma unroll 8
        for (int q = 0; q < 16; q++) {
            float4 v = *(const float4*)(src + q * 4);
            unsigned h0, l0, h1, l1;
            cvt_pair(v.x, v.y, h0, l0);
            cvt_pair(v.z, v.w, h1, l1);
            *(uint2*)(dh + q * 8) = make_uint2(h0, h1);
            *(uint2*)(dl + q * 8) = make_uint2(l0, l1);
        }
    }
    unsigned tgt = 0;
    group_sync(mt, tgt += 16);

    const float* hrow  = g_h  + (size_t)mt * 32 * H_;
    const float* rhrow = g_rh + (size_t)mt * 32 * H_;

    const int pr  = tid >> 3;
    const int pks = (tid & 7) * 16;

    const int aHb = SM_AH + (wm * 16 + g) * AROW + tg * 4;
    const int aLb = SM_AL + (wm * 16 + g) * AROW + tg * 4;
    const int bgH0 = SM_WGH + (wn * 16 + g) * WROW + tg * 4;
    const int bgH1 = SM_WGH + (wn * 16 + 8 + g) * WROW + tg * 4;
    const int bgL0 = SM_WGL + (wn * 16 + g) * WROW + tg * 4;
    const int bgL1 = SM_WGL + (wn * 16 + 8 + g) * WROW + tg * 4;
    const int bhH  = SM_WHH + (wn * 8 + g) * WROW + tg * 4;
    const int bhL  = SM_WHL + (wn * 8 + g) * WROW + tg * 4;

    const int r0 = mt * 32 + wm * 16 + g;

    for (int t = 0; t < S_; t++) {
        // ===================== GATE PHASE =====================
        float cg0[4] = {0.f, 0.f, 0.f, 0.f};
        float cg1[4] = {0.f, 0.f, 0.f, 0.f};
        float4 pf[4];
        #pragma unroll
        for (int q = 0; q < 4; q++)
            pf[q] = __ldcg((const float4*)(hrow + (size_t)pr * H_ + pks + q * 4));

        #pragma unroll 1
        for (int c = 0; c < 4; c++) {
            {
                char* dh = smc + SM_AH + pr * AROW + pks * 2;
                char* dl = smc + SM_AL + pr * AROW + pks * 2;
                #pragma unroll
                for (int q = 0; q < 4; q++) {
                    unsigned h0, l0, h1, l1;
                    cvt_pair(pf[q].x, pf[q].y, h0, l0);
                    cvt_pair(pf[q].z, pf[q].w, h1, l1);
                    *(uint2*)(dh + q * 8) = make_uint2(h0, h1);
                    *(uint2*)(dl + q * 8) = make_uint2(l0, l1);
                }
            }
            __syncthreads();
            if (c < 3) {
                #pragma unroll
                for (int q = 0; q < 4; q++)
                    pf[q] = __ldcg((const float4*)(hrow + (size_t)pr * H_
                                                   + (c + 1) * 128 + pks + q * 4));
            }
            const int kwb = c * 256;
            #pragma unroll
            for (int s = 0; s < 8; s++) {
                const int ka = s * 32;
                const int kw = kwb + s * 32;
                unsigned aH0 = *(const unsigned*)(smc + aHb + ka);
                unsigned aH1 = *(const unsigned*)(smc + aHb + 8 * AROW + ka);
                unsigned aH2 = *(const unsigned*)(smc + aHb + ka + 16);
                unsigned aH3 = *(const unsigned*)(smc + aHb + 8 * AROW + ka + 16);
                unsigned aL0 = *(const unsigned*)(smc + aLb + ka);
                unsigned aL1 = *(const unsigned*)(smc + aLb + 8 * AROW + ka);
                unsigned aL2 = *(const unsigned*)(smc + aLb + ka + 16);
                unsigned aL3 = *(const unsigned*)(smc + aLb + 8 * AROW + ka + 16);
                unsigned b0h0 = *(const unsigned*)(smc + bgH0 + kw);
                unsigned b0h1 = *(const unsigned*)(smc + bgH0 + kw + 16);
                unsigned b0l0 = *(const unsigned*)(smc + bgL0 + kw);
                unsigned b0l1 = *(const unsigned*)(smc + bgL0 + kw + 16);
                unsigned b1h0 = *(const unsigned*)(smc + bgH1 + kw);
                unsigned b1h1 = *(const unsigned*)(smc + bgH1 + kw + 16);
                unsigned b1l0 = *(const unsigned*)(smc + bgL1 + kw);
                unsigned b1l1 = *(const unsigned*)(smc + bgL1 + kw + 16);
                mma16816(cg0, aH0, aH1, aH2, aH3, b0h0, b0h1);
                mma16816(cg0, aH0, aH1, aH2, aH3, b0l0, b0l1);
                mma16816(cg0, aL0, aL1, aL2, aL3, b0h0, b0h1);
                mma16816(cg1, aH0, aH1, aH2, aH3, b1h0, b1h1);
                mma16816(cg1, aH0, aH1, aH2, aH3, b1l0, b1l1);
                mma16816(cg1, aL0, aL1, aL2, aL3, b1h0, b1h1);
            }
            if (c < 3) __syncthreads();
        }
        {
            const float* Gxt = g_Gx + (size_t)t * B_ * H2_;
            #pragma unroll
            for (int tile = 0; tile < 2; tile++) {
                float* cc = tile ? cg1 : cg0;
                int n = nt * 64 + wn * 16 + tile * 8 + tg * 2;
                float2 gx0 = __ldcg((const float2*)(Gxt + (size_t)r0 * H2_ + n));
                float2 gx1 = __ldcg((const float2*)(Gxt + (size_t)(r0 + 8) * H2_ + n));
                float v00 = sigm(cc[0] + gx0.x), v01 = sigm(cc[1] + gx0.y);
                float v10 = sigm(cc[2] + gx1.x), v11 = sigm(cc[3] + gx1.y);
                if (nt < 8) {
                    __stcg((float2*)(g_z + r0 * H_ + n), make_float2(v00, v01));
                    __stcg((float2*)(g_z + (r0 + 8) * H_ + n), make_float2(v10, v11));
                } else {
                    int n2 = n - H_;
                    float2 hv0 = __ldcg((const float2*)(g_h + r0 * H_ + n2));
                    float2 hv1 = __ldcg((const float2*)(g_h + (r0 + 8) * H_ + n2));
                    __stcg((float2*)(g_rh + r0 * H_ + n2),
                           make_float2(v00 * hv0.x, v01 * hv0.y));
                    __stcg((float2*)(g_rh + (r0 + 8) * H_ + n2),
                           make_float2(v10 * hv1.x, v11 * hv1.y));
                }
            }
        }
        group_sync(mt, tgt += 16);

        // ===================== CANDIDATE PHASE =====================
        float cc[4] = {0.f, 0.f, 0.f, 0.f};
        #pragma unroll
        for (int q = 0; q < 4; q++)
            pf[q] = __ldcg((const float4*)(rhrow + (size_t)pr * H_ + pks + q * 4));

        #pragma unroll 1
        for (int c = 0; c < 4; c++) {
            {
                char* dh = smc + SM_AH + pr * AROW + pks * 2;
                char* dl = smc + SM_AL + pr * AROW + pks * 2;
                #pragma unroll
                for (int q = 0; q < 4; q++) {
                    unsigned h0, l0, h1, l1;
                    cvt_pair(pf[q].x, pf[q].y, h0, l0);
                    cvt_pair(pf[q].z, pf[q].w, h1, l1);
                    *(uint2*)(dh + q * 8) = make_uint2(h0, h1);
                    *(uint2*)(dl + q * 8) = make_uint2(l0, l1);
                }
            }
            __syncthreads();
            if (c < 3) {
                #pragma unroll
                for (int q = 0; q < 4; q++)
                    pf[q] = __ldcg((const float4*)(rhrow + (size_t)pr * H_
                                                   + (c + 1) * 128 + pks + q * 4));
            }
            const int kwb = c * 256;
            #pragma unroll
            for (int s = 0; s < 8; s++) {
                const int ka = s * 32;
                const int kw = kwb + s * 32;
                unsigned aH0 = *(const unsigned*)(smc + aHb + ka);
                unsigned aH1 = *(const unsigned*)(smc + aHb + 8 * AROW + ka);
                unsigned aH2 = *(const unsigned*)(smc + aHb + ka + 16);
                unsigned aH3 = *(const unsigned*)(smc + aHb + 8 * AROW + ka + 16);
                unsigned aL0 = *(const unsigned*)(smc + aLb + ka);
                unsigned aL1 = *(const unsigned*)(smc + aLb + 8 * AROW + ka);
                unsigned aL2 = *(const unsigned*)(smc + aLb + ka + 16);
                unsigned aL3 = *(const unsigned*)(smc + aLb + 8 * AROW + ka + 16);
                unsigned bh0 = *(const unsigned*)(smc + bhH + kw);
                unsigned bh1 = *(const unsigned*)(smc + bhH + kw + 16);
                unsigned bl0 = *(const unsigned*)(smc + bhL + kw);
                unsigned bl1 = *(const unsigned*)(smc + bhL + kw + 16);
                mma16816(cc, aH0, aH1, aH2, aH3, bh0, bh1);
                mma16816(cc, aH0, aH1, aH2, aH3, bl0, bl1);
                mma16816(cc, aL0, aL1, aL2, aL3, bh0, bh1);
            }
            if (c < 3) __syncthreads();
        }
        {
            float* hall_t = g_hall + (size_t)t * B_ * H_;
            const float* Cxt = g_Cx + (size_t)t * B_ * H_;
            int n = nt * 32 + wn * 8 + tg * 2;
            #pragma unroll
            for (int rr = 0; rr < 2; rr++) {
                int r = r0 + rr * 8;
                size_t idx = (size_t)r * H_ + n;
                float2 cx = __ldcg((const float2*)(Cxt + idx));
                float2 zz = __ldcg((const float2*)(g_z + idx));
                float2 hh = __ldcg((const float2*)(g_h + idx));
                float c0 = tanh_fast(cc[rr * 2 + 0] + cx.x);
                float c1 = tanh_fast(cc[rr * 2 + 1] + cx.y);
                float2 hn = make_float2(fmaf(zz.x, c0 - hh.x, hh.x),
                                        fmaf(zz.y, c1 - hh.y, hh.y));
                __stcg((float2*)(g_h + idx), hn);
                __stcg((float2*)(hall_t + idx), hn);
            }
        }
        group_sync(mt, tgt += 16);
    }
}

// ---------------------------------------------------------------------------
__global__ void gather_embed(const int* __restrict__ x,
                             const float* __restrict__ emb) {
    if (blockIdx.x == 0 && threadIdx.x < 8 * 32)
        g_gcnt[threadIdx.x] = 0;   // reset group-barrier counters each launch
    int idx = blockIdx.x * 256 + threadIdx.x;
    int h4  = idx & (H_ / 4 - 1);
    int row = idx >> 7;
    int b   = row & (B_ - 1);
    int s   = row >> 8;
    int tok = x[b * S_ + s];
    reinterpret_cast<float4*>(g_xe)[(size_t)row * (H_ / 4) + h4] =
        reinterpret_cast<const float4*>(emb)[(size_t)tok * (H_ / 4) + h4];
}

__global__ void copy_hfinal(float* __restrict__ out) {
    int i = blockIdx.x * 256 + threadIdx.x;
    out[i] = g_h[i];
}

// ---------------------------------------------------------------------------
extern "C" void kernel_launch(void* const* d_in, const int* in_sizes, int n_in,
                              void* d_out, int out_size) {
    (void)in_sizes; (void)n_in; (void)out_size;
    const int*   x   = (const int*)  d_in[0];
    const float* emb = (const float*)d_in[1];
    const float* Wg  = (const float*)d_in[2];
    const float* bg  = (const float*)d_in[3];
    const float* Wh  = (const float*)d_in[4];
    const float* bh  = (const float*)d_in[5];
    const float* Wo  = (const float*)d_in[6];
    const float* bo  = (const float*)d_in[7];
    float* out = (float*)d_out;

    static int smem_set = 0;
    if (!smem_set) {
        cudaFuncSetAttribute(gru_persist,
                             cudaFuncAttributeMaxDynamicSharedMemorySize,
                             GRU_SMEM);
        smem_set = 1;
    }

    gather_embed<<<(S_ * B_ * (H_ / 4)) / 256, 256>>>(x, emb);

    sgemm_tc<<<dim3(H2_ / 128, 65536 / 128), 256>>>(0, Wg, H2_, bg, 0, nullptr);
    sgemm_tc<<<dim3(H_  / 128, 65536 / 128), 256>>>(0, Wh, H2_, bh, 1, nullptr);

    gru_persist<<<128, 256, GRU_SMEM>>>(Wg, Wh);

    sgemm_tc<<<dim3(O_ / 128, 65536 / 128), 256>>>(1, Wo, H_, bo, 2,
                                                   out + (size_t)B_ * H_);
    copy_hfinal<<<(B_ * H_) / 256, 256>>>(out);
}